// round 8
// baseline (speedup 1.0000x reference)
#include <cuda_runtime.h>
#include <math.h>

#define NHIT 80000
#define TILE 64
#define NBLK 1252              // 1252 * 64 = 80128
#define NPAD (NBLK * TILE)
#define KOBJ 512
#define KHALF 256
#define HBLK 313               // k_hits blocks (256 thr)

// ---------------- scratch (device globals; zero at load, reset after use) ----------
__device__ float4 g_hit[NPAD];                 // x, y, q, t_idx (int bits)
__device__ float4 g_alpha[KOBJ];               // x_a, y_a, q_a, beta_a
__device__ unsigned long long g_amax[KOBJ];    // packed (beta_bits<<32 | ~idx)
__device__ int    g_cnt[KOBJ];
__device__ float2 g_numden[KOBJ];              // payload num, den
__device__ float  g_att[KOBJ], g_rep[KOBJ];
__device__ float  g_noise_sum, g_noise_cnt, g_cc_sum;
__device__ unsigned g_done_h, g_done_p;

__device__ __forceinline__ float clampb(float b) {
    return fminf(fmaxf(b, 1e-6f), 1.0f - 1e-6f);
}
__device__ __forceinline__ float softclip_f(float x, float c) {
    x = x * (1.0f / c);
    if (x > 1.0f) x = __logf(x + 1.0f);
    return x * c;
}
__device__ __forceinline__ float huber_f(float x, float d) {
    float ax = fabsf(x);
    return ax < d ? x * x : d * d + 2.0f * d * (ax - d);
}
__device__ __forceinline__ float sqapx(float x) {
    float s; asm("sqrt.approx.f32 %0, %1;" : "=f"(s) : "f"(x)); return s;
}

// unmasked hinge-accumulate: rep += sat(1 - sqrt(d2)) * q   (one fused asm block)
#define REP_ACC(D2, Q, REP)                                         \
    asm("{ .reg .f32 s;\n\t"                                        \
        " sqrt.approx.f32 s, %1;\n\t"                               \
        " sub.rn.sat.f32 s, 0f3F800000, s;\n\t"                     \
        " fma.rn.f32 %0, s, %2, %0;\n\t}"                           \
        : "+f"(REP) : "f"(D2), "f"(Q));

// ---------------- kernel 1: per-hit pass + fused alpha gather ----------------
__global__ void __launch_bounds__(256) k_hits(
        const float* __restrict__ pb,  const float* __restrict__ cc,
        const float* __restrict__ pe,  const float* __restrict__ pp,
        const float* __restrict__ pt,  const float* __restrict__ pid,
        const int*   __restrict__ tix, const float* __restrict__ te,
        const float* __restrict__ tp,  const float* __restrict__ tt) {
    __shared__ unsigned s_last;
    int i = blockIdx.x * blockDim.x + threadIdx.x;
    float ns = 0.0f, ncnt = 0.0f, ccs = 0.0f;
    if (i < NHIT) {   // warp-uniform (80000 % 32 == 0)
        // ---- hoist ALL loads: ~12 independent LDGs in flight ----
        float  braw = pb[i];
        int    t    = tix[i];
        float2 ccv  = ((const float2*)cc)[i];
        float  pev  = pe[i];
        float2 ppv  = ((const float2*)pp)[i];
        float  ptv  = pt[i];
        float  tev  = te[i];
        float2 tpv  = ((const float2*)tp)[i];
        float  ttv  = tt[i];
        float2 pid0 = ((const float2*)pid)[3 * i];
        float2 pid1 = ((const float2*)pid)[3 * i + 1];
        float2 pid2 = ((const float2*)pid)[3 * i + 2];

        float beta = clampb(braw);
        // atanh(b)^2 = 0.25 * ln^2((1+b)/(1-b))
        float lg = __logf(__fdividef(1.0f + beta, 1.0f - beta));
        float q = fmaf(0.25f * lg, lg, 0.1f);
        g_hit[i] = make_float4(ccv.x, ccv.y, q, __int_as_float(t));
        ccs = ccv.x * ccv.x + ccv.y * ccv.y;

        // ---- payload (computed unconditionally; ~0.2% waste on noise) ----
        float ed = fabsf(tev - pev);
        float el = softclip_f(fmaf(10.0f, __expf(-0.1f * ed * ed), 0.01f * ed), 10.0f);
        float dx = tpv.x - ppv.x, dy = tpv.y - ppv.y;
        float pl = softclip_f(huber_f(sqrtf(fmaf(dx, dx, dy * dy) * 0.01f + 0.01f), 10.0f), 3.0f);
        float tl = softclip_f(huber_f(ttv - ptv, 2.0f), 6.0f);
        float s2 = pid0.x * pid0.x + pid0.y * pid0.y + pid1.x * pid1.x
                 + pid1.y * pid1.y + pid2.x * pid2.x + pid2.y * pid2.y;
        float cl = 1e-8f * (s2 * (1.0f / 6.0f));
        float payload = el + pl + tl + cl;
        float w = tev > 10.0f ? 1.0f : fmaxf((tev - 0.5f) * (1.0f / 9.5f), 0.0f);
        float pw = beta * w;

        if (t >= 0) {
            atomicAdd(&g_cnt[t], 1);
            // argmax beta, ties -> lowest index (matches jnp.argmax)
            unsigned long long key =
                (((unsigned long long)__float_as_uint(beta)) << 32) |
                (unsigned long long)(0xFFFFFFFFu - (unsigned)i);
            atomicMax(&g_amax[t], key);
            // fused num+den reduction (one L2 atomic instead of two)
            asm volatile("red.global.add.v2.f32 [%0], {%1, %2};"
                         :: "l"(&g_numden[t]), "f"(payload * pw), "f"(pw) : "memory");
        } else {
            ns = beta; ncnt = 1.0f;
        }
    } else {
        g_hit[i] = make_float4(0.0f, 0.0f, 0.0f, __int_as_float(-1));  // inert pad
    }
    #pragma unroll
    for (int o = 16; o > 0; o >>= 1) {
        ns   += __shfl_down_sync(0xFFFFFFFF, ns, o);
        ncnt += __shfl_down_sync(0xFFFFFFFF, ncnt, o);
        ccs  += __shfl_down_sync(0xFFFFFFFF, ccs, o);
    }
    if ((threadIdx.x & 31) == 0) {
        if (ns != 0.0f || ncnt != 0.0f) { atomicAdd(&g_noise_sum, ns); atomicAdd(&g_noise_cnt, ncnt); }
        atomicAdd(&g_cc_sum, ccs);
    }

    // ---- last block gathers condensation points (replaces k_alpha launch) ----
    __threadfence();
    if (threadIdx.x == 0) s_last = atomicAdd(&g_done_h, 1u);
    __syncthreads();
    if (s_last != gridDim.x - 1) return;

    #pragma unroll
    for (int kk = 0; kk < 2; kk++) {
        int k = threadIdx.x + kk * 256;
        if (g_cnt[k] > 0) {
            unsigned idx = 0xFFFFFFFFu - (unsigned)(g_amax[k] & 0xFFFFFFFFull);
            float b = clampb(pb[idx]);
            float lg = __logf(__fdividef(1.0f + b, 1.0f - b));
            float2 ccv = ((const float2*)cc)[idx];
            g_alpha[k] = make_float4(ccv.x, ccv.y, fmaf(0.25f * lg, lg, 0.1f), b);
        } else {
            g_alpha[k] = make_float4(0.0f, 0.0f, 0.0f, 1.0f);
        }
    }
    if (threadIdx.x == 0) g_done_h = 0u;   // reset for next graph replay
}

// ---------------- kernel 2: unmasked repulsion N x K + O(N) att/correction ----------
__global__ void __launch_bounds__(KHALF, 8) k_pairs(float* __restrict__ out) {
    __shared__ float4 sh[TILE];
    __shared__ float s_red[2 * KHALF];
    __shared__ unsigned s_last;

    const int t = threadIdx.x;
    const int k0 = t;
    const int k1 = t + KHALF;

    float4 a0 = g_alpha[k0];
    float4 a1 = g_alpha[k1];

    float rep0 = 0.f, rep1 = 0.f;
    const int base = blockIdx.x * TILE;
    if (t < TILE) sh[t] = g_hit[base + t];
    __syncthreads();

    // ---- hot loop: pure unmasked repulsion, 2 objects per thread ----
    #pragma unroll 16
    for (int j = 0; j < TILE; j++) {
        float4 h = sh[j];                           // broadcast LDS.128
        {
            float dx = h.x - a0.x, dy = h.y - a0.y;
            float d2 = fmaf(dx, dx, fmaf(dy, dy, 1e-6f));
            REP_ACC(d2, h.z, rep0)
        }
        {
            float dx = h.x - a1.x, dy = h.y - a1.y;
            float d2 = fmaf(dx, dx, fmaf(dy, dy, 1e-6f));
            REP_ACC(d2, h.z, rep1)
        }
    }

    if (a0.z > 0.f) atomicAdd(&g_rep[k0], rep0 * a0.z);
    if (a1.z > 0.f) atomicAdd(&g_rep[k1], rep1 * a1.z);

    // ---- O(N) part AFTER hot loop: attraction + member-repulsion correction ----
    if (t < TILE) {
        float4 h = sh[t];
        int ti = __float_as_int(h.w);
        if (ti >= 0) {
            float4 a = g_alpha[ti];               // 8KB table, L1/L2-hot
            float dx = h.x - a.x, dy = h.y - a.y;
            float d2e = fmaf(dx, dx, fmaf(dy, dy, 1e-6f));
            float d2  = fmaf(dx, dx, dy * dy);    // reference att uses d2 w/o eps
            float r = __saturatef(1.0f - sqapx(d2e));   // same formula as hot loop
            atomicAdd(&g_att[ti],  d2 * h.z * a.z);
            atomicAdd(&g_rep[ti], -r  * h.z * a.z);     // remove member pair
        }
    }

    // --- last block finalizes + resets scratch for next graph replay ---
    __threadfence();
    if (t == 0) s_last = atomicAdd(&g_done_p, 1u);
    __syncthreads();
    if (s_last != gridDim.x - 1) return;

    float obj = 0.f, has = 0.f;
    #pragma unroll
    for (int kk = 0; kk < 2; kk++) {
        int k = t + kk * KHALF;
        int c = g_cnt[k];
        if (c > 0) {
            has += 1.0f;
            float fc = (float)c;
            float2 nd = g_numden[k];
            obj += g_att[k] / (fc + 1e-9f)
                 + g_rep[k] / ((float)NHIT - fc + 1e-9f)
                 + nd.x / (nd.y + 1e-9f)
                 + (1.0f - g_alpha[k].w);
        }
        g_amax[k] = 0ull; g_cnt[k] = 0;
        g_numden[k] = make_float2(0.f, 0.f); g_att[k] = 0.f; g_rep[k] = 0.f;
    }
    s_red[t] = obj; s_red[t + KHALF] = has;
    __syncthreads();
    #pragma unroll
    for (int o = KHALF / 2; o > 0; o >>= 1) {
        if (t < o) { s_red[t] += s_red[t + o]; s_red[t + KHALF] += s_red[t + KHALF + o]; }
        __syncthreads();
    }
    if (t == 0) {
        float n_obj = s_red[KHALF] + 1e-9f;
        float total = s_red[0] / n_obj
                    + g_noise_sum / (g_noise_cnt + 1e-9f)
                    + 0.001f * g_cc_sum * (1.0f / (float)(NHIT * 2));
        out[0] = total;
        g_noise_sum = 0.f; g_noise_cnt = 0.f; g_cc_sum = 0.f; g_done_p = 0u;
    }
}

// ---------------- launch ----------------
extern "C" void kernel_launch(void* const* d_in, const int* in_sizes, int n_in,
                              void* d_out, int out_size) {
    const float* pb  = (const float*)d_in[0];
    const float* cc  = (const float*)d_in[1];
    const float* pe  = (const float*)d_in[2];
    const float* pp  = (const float*)d_in[3];
    const float* pt  = (const float*)d_in[4];
    const float* pid = (const float*)d_in[5];
    const int*   tix = (const int*)  d_in[6];
    const float* te  = (const float*)d_in[7];
    const float* tp  = (const float*)d_in[8];
    const float* tt  = (const float*)d_in[9];

    k_hits<<<HBLK, 256>>>(pb, cc, pe, pp, pt, pid, tix, te, tp, tt);
    k_pairs<<<NBLK, KHALF>>>((float*)d_out);
}

// round 9
// speedup vs baseline: 1.3674x; 1.3674x over previous
#include <cuda_runtime.h>
#include <math.h>

#define NHIT 80000
#define TILE 128
#define NBLK 626               // 626 * 128 = 80128
#define NPAD (NBLK * TILE)
#define KOBJ 512
#define KHALF 256
#define HBLK 313               // k_hits blocks (256 thr)

// ---------------- scratch (device globals; zero at load, reset after use) ----------
__device__ float4 g_hit[NPAD];                 // x, y, q, t_idx (int bits)
__device__ float4 g_alpha[KOBJ];               // x_a, y_a, q_a, beta_a
__device__ unsigned long long g_amax[KOBJ];    // packed (beta_bits<<32 | ~idx)
__device__ int    g_cnt[KOBJ];
__device__ float2 g_numden[KOBJ];              // payload num, den
__device__ float  g_att[KOBJ], g_rep[KOBJ];
__device__ float  g_noise_sum, g_noise_cnt, g_cc_sum;
__device__ unsigned g_done_h, g_done_p;

__device__ __forceinline__ float clampb(float b) {
    return fminf(fmaxf(b, 1e-6f), 1.0f - 1e-6f);
}
__device__ __forceinline__ float softclip_f(float x, float c) {
    x = x * (1.0f / c);
    if (x > 1.0f) x = __logf(x + 1.0f);
    return x * c;
}
__device__ __forceinline__ float huber_f(float x, float d) {
    float ax = fabsf(x);
    return ax < d ? x * x : d * d + 2.0f * d * (ax - d);
}
__device__ __forceinline__ float sqapx(float x) {
    float s; asm("sqrt.approx.f32 %0, %1;" : "=f"(s) : "f"(x)); return s;
}

// unmasked hinge-accumulate: rep += sat(1 - sqrt(d2)) * q   (one fused asm block)
#define REP_ACC(D2, Q, REP)                                         \
    asm("{ .reg .f32 s;\n\t"                                        \
        " sqrt.approx.f32 s, %1;\n\t"                               \
        " sub.rn.sat.f32 s, 0f3F800000, s;\n\t"                     \
        " fma.rn.f32 %0, s, %2, %0;\n\t}"                           \
        : "+f"(REP) : "f"(D2), "f"(Q));

// both objects for one staged hit
#define PAIR2(H)                                                    \
    {                                                               \
        float dx0 = (H).x - a0.x, dy0 = (H).y - a0.y;               \
        float d20 = fmaf(dx0, dx0, fmaf(dy0, dy0, 1e-6f));          \
        float dx1 = (H).x - a1.x, dy1 = (H).y - a1.y;               \
        float d21 = fmaf(dx1, dx1, fmaf(dy1, dy1, 1e-6f));          \
        REP_ACC(d20, (H).z, rep0)                                   \
        REP_ACC(d21, (H).z, rep1)                                   \
    }

// ---------------- kernel 1: per-hit pass + fused alpha gather ----------------
__global__ void __launch_bounds__(256) k_hits(
        const float* __restrict__ pb,  const float* __restrict__ cc,
        const float* __restrict__ pe,  const float* __restrict__ pp,
        const float* __restrict__ pt,  const float* __restrict__ pid,
        const int*   __restrict__ tix, const float* __restrict__ te,
        const float* __restrict__ tp,  const float* __restrict__ tt) {
    __shared__ unsigned s_last;
    int i = blockIdx.x * blockDim.x + threadIdx.x;
    float ns = 0.0f, ncnt = 0.0f, ccs = 0.0f;
    if (i < NHIT) {   // warp-uniform (80000 % 32 == 0)
        // ---- hoist ALL loads: ~12 independent LDGs in flight ----
        float  braw = pb[i];
        int    t    = tix[i];
        float2 ccv  = ((const float2*)cc)[i];
        float  pev  = pe[i];
        float2 ppv  = ((const float2*)pp)[i];
        float  ptv  = pt[i];
        float  tev  = te[i];
        float2 tpv  = ((const float2*)tp)[i];
        float  ttv  = tt[i];
        float2 pid0 = ((const float2*)pid)[3 * i];
        float2 pid1 = ((const float2*)pid)[3 * i + 1];
        float2 pid2 = ((const float2*)pid)[3 * i + 2];

        float beta = clampb(braw);
        // atanh(b)^2 = 0.25 * ln^2((1+b)/(1-b))
        float lg = __logf(__fdividef(1.0f + beta, 1.0f - beta));
        float q = fmaf(0.25f * lg, lg, 0.1f);
        g_hit[i] = make_float4(ccv.x, ccv.y, q, __int_as_float(t));
        ccs = ccv.x * ccv.x + ccv.y * ccv.y;

        // ---- payload (computed unconditionally; ~0.2% waste on noise) ----
        float ed = fabsf(tev - pev);
        float el = softclip_f(fmaf(10.0f, __expf(-0.1f * ed * ed), 0.01f * ed), 10.0f);
        float dx = tpv.x - ppv.x, dy = tpv.y - ppv.y;
        float pl = softclip_f(huber_f(sqrtf(fmaf(dx, dx, dy * dy) * 0.01f + 0.01f), 10.0f), 3.0f);
        float tl = softclip_f(huber_f(ttv - ptv, 2.0f), 6.0f);
        float s2 = pid0.x * pid0.x + pid0.y * pid0.y + pid1.x * pid1.x
                 + pid1.y * pid1.y + pid2.x * pid2.x + pid2.y * pid2.y;
        float cl = 1e-8f * (s2 * (1.0f / 6.0f));
        float payload = el + pl + tl + cl;
        float w = tev > 10.0f ? 1.0f : fmaxf((tev - 0.5f) * (1.0f / 9.5f), 0.0f);
        float pw = beta * w;

        if (t >= 0) {
            atomicAdd(&g_cnt[t], 1);
            // argmax beta, ties -> lowest index (matches jnp.argmax)
            unsigned long long key =
                (((unsigned long long)__float_as_uint(beta)) << 32) |
                (unsigned long long)(0xFFFFFFFFu - (unsigned)i);
            atomicMax(&g_amax[t], key);
            // fused num+den reduction (one L2 atomic instead of two)
            asm volatile("red.global.add.v2.f32 [%0], {%1, %2};"
                         :: "l"(&g_numden[t]), "f"(payload * pw), "f"(pw) : "memory");
        } else {
            ns = beta; ncnt = 1.0f;
        }
    } else {
        g_hit[i] = make_float4(0.0f, 0.0f, 0.0f, __int_as_float(-1));  // inert pad
    }
    #pragma unroll
    for (int o = 16; o > 0; o >>= 1) {
        ns   += __shfl_down_sync(0xFFFFFFFF, ns, o);
        ncnt += __shfl_down_sync(0xFFFFFFFF, ncnt, o);
        ccs  += __shfl_down_sync(0xFFFFFFFF, ccs, o);
    }
    if ((threadIdx.x & 31) == 0) {
        if (ns != 0.0f || ncnt != 0.0f) { atomicAdd(&g_noise_sum, ns); atomicAdd(&g_noise_cnt, ncnt); }
        atomicAdd(&g_cc_sum, ccs);
    }

    // ---- last block gathers condensation points (replaces k_alpha launch) ----
    __threadfence();
    if (threadIdx.x == 0) s_last = atomicAdd(&g_done_h, 1u);
    __syncthreads();
    if (s_last != gridDim.x - 1) return;

    #pragma unroll
    for (int kk = 0; kk < 2; kk++) {
        int k = threadIdx.x + kk * 256;
        if (g_cnt[k] > 0) {
            unsigned idx = 0xFFFFFFFFu - (unsigned)(g_amax[k] & 0xFFFFFFFFull);
            float b = clampb(pb[idx]);
            float lg = __logf(__fdividef(1.0f + b, 1.0f - b));
            float2 ccv = ((const float2*)cc)[idx];
            g_alpha[k] = make_float4(ccv.x, ccv.y, fmaf(0.25f * lg, lg, 0.1f), b);
        } else {
            g_alpha[k] = make_float4(0.0f, 0.0f, 0.0f, 1.0f);
        }
    }
    if (threadIdx.x == 0) g_done_h = 0u;   // reset for next graph replay
}

// ---------------- kernel 2: unmasked repulsion N x K + O(N) att/correction ----------
// launch_bounds(256, 4): allow up to 64 regs so the 8-deep register staging fits.
__global__ void __launch_bounds__(KHALF, 4) k_pairs(float* __restrict__ out) {
    __shared__ float4 sh[TILE];
    __shared__ float s_red[2 * KHALF];
    __shared__ unsigned s_last;

    const int t = threadIdx.x;
    const int k0 = t;
    const int k1 = t + KHALF;

    float4 a0 = g_alpha[k0];
    float4 a1 = g_alpha[k1];

    float rep0 = 0.f, rep1 = 0.f;
    const int base = blockIdx.x * TILE;
    if (t < TILE) sh[t] = g_hit[base + t];
    __syncthreads();

    // ---- hot loop: stage 8 hits in registers (8 back-to-back LDS.128, MLP=8),
    //      then 16 pair-updates with 8 independent MUFU chains in flight ----
    #pragma unroll 1
    for (int j = 0; j < TILE; j += 8) {
        float4 h0 = sh[j + 0];
        float4 h1 = sh[j + 1];
        float4 h2 = sh[j + 2];
        float4 h3 = sh[j + 3];
        float4 h4 = sh[j + 4];
        float4 h5 = sh[j + 5];
        float4 h6 = sh[j + 6];
        float4 h7 = sh[j + 7];
        PAIR2(h0) PAIR2(h1) PAIR2(h2) PAIR2(h3)
        PAIR2(h4) PAIR2(h5) PAIR2(h6) PAIR2(h7)
    }

    if (a0.z > 0.f) atomicAdd(&g_rep[k0], rep0 * a0.z);
    if (a1.z > 0.f) atomicAdd(&g_rep[k1], rep1 * a1.z);

    // ---- O(N) part AFTER hot loop: attraction + member-repulsion correction ----
    if (t < TILE) {
        float4 h = sh[t];
        int ti = __float_as_int(h.w);
        if (ti >= 0) {
            float4 a = g_alpha[ti];               // 8KB table, L1/L2-hot
            float dx = h.x - a.x, dy = h.y - a.y;
            float d2e = fmaf(dx, dx, fmaf(dy, dy, 1e-6f));
            float d2  = fmaf(dx, dx, dy * dy);    // reference att uses d2 w/o eps
            float r = __saturatef(1.0f - sqapx(d2e));   // same formula as hot loop
            atomicAdd(&g_att[ti],  d2 * h.z * a.z);
            atomicAdd(&g_rep[ti], -r  * h.z * a.z);     // remove member pair
        }
    }

    // --- last block finalizes + resets scratch for next graph replay ---
    __threadfence();
    if (t == 0) s_last = atomicAdd(&g_done_p, 1u);
    __syncthreads();
    if (s_last != gridDim.x - 1) return;

    float obj = 0.f, has = 0.f;
    #pragma unroll
    for (int kk = 0; kk < 2; kk++) {
        int k = t + kk * KHALF;
        int c = g_cnt[k];
        if (c > 0) {
            has += 1.0f;
            float fc = (float)c;
            float2 nd = g_numden[k];
            obj += g_att[k] / (fc + 1e-9f)
                 + g_rep[k] / ((float)NHIT - fc + 1e-9f)
                 + nd.x / (nd.y + 1e-9f)
                 + (1.0f - g_alpha[k].w);
        }
        g_amax[k] = 0ull; g_cnt[k] = 0;
        g_numden[k] = make_float2(0.f, 0.f); g_att[k] = 0.f; g_rep[k] = 0.f;
    }
    s_red[t] = obj; s_red[t + KHALF] = has;
    __syncthreads();
    #pragma unroll
    for (int o = KHALF / 2; o > 0; o >>= 1) {
        if (t < o) { s_red[t] += s_red[t + o]; s_red[t + KHALF] += s_red[t + KHALF + o]; }
        __syncthreads();
    }
    if (t == 0) {
        float n_obj = s_red[KHALF] + 1e-9f;
        float total = s_red[0] / n_obj
                    + g_noise_sum / (g_noise_cnt + 1e-9f)
                    + 0.001f * g_cc_sum * (1.0f / (float)(NHIT * 2));
        out[0] = total;
        g_noise_sum = 0.f; g_noise_cnt = 0.f; g_cc_sum = 0.f; g_done_p = 0u;
    }
}

// ---------------- launch ----------------
extern "C" void kernel_launch(void* const* d_in, const int* in_sizes, int n_in,
                              void* d_out, int out_size) {
    const float* pb  = (const float*)d_in[0];
    const float* cc  = (const float*)d_in[1];
    const float* pe  = (const float*)d_in[2];
    const float* pp  = (const float*)d_in[3];
    const float* pt  = (const float*)d_in[4];
    const float* pid = (const float*)d_in[5];
    const int*   tix = (const int*)  d_in[6];
    const float* te  = (const float*)d_in[7];
    const float* tp  = (const float*)d_in[8];
    const float* tt  = (const float*)d_in[9];

    k_hits<<<HBLK, 256>>>(pb, cc, pe, pp, pt, pid, tix, te, tp, tt);
    k_pairs<<<NBLK, KHALF>>>((float*)d_out);
}